// round 1
// baseline (speedup 1.0000x reference)
#include <cuda_runtime.h>
#include <cuda_bf16.h>
#include <math.h>

// ---------------------------------------------------------------------------
// GCN pipeline:
//   h1 = relu( GraphConv(x, W1, b1) )        [N,80]
//   h2 = relu( GraphConv(h1, W2, b2) )       [N,40]
//   t  = tanh( mean_n(h2) @ Wa )             [40]   (mean commutes with @)
//   s  = sigmoid(h2 @ t)                     [N]
//   rep= h2^T @ s                            [40]
//   out= MLP(rep)                            [1]
// GraphConv(norm='both'): y = D_in^-1/2 * scatter_dst( (x * D_out^-1/2)[src] @ W ) + b
// Row-scalar commutes: compute (x @ W) * norm_s, gather via dst-CSR, * norm_d + b.
// ---------------------------------------------------------------------------

#define MAXN 100000
#define MAXE 3200000

__device__ __align__(16) float g_bufA[MAXN * 80];   // h0 [N,80]; later h1b [N,40]
__device__ __align__(16) float g_bufB[MAXN * 80];   // h1 [N,80]; later h2  [N,40]
__device__ int   g_inc[MAXN];
__device__ int   g_outc[MAXN];
__device__ int   g_rowptr[MAXN + 1];
__device__ int   g_cursor[MAXN];
__device__ int   g_esrc[MAXE];
__device__ float g_norm_s[MAXN];
__device__ float g_norm_d[MAXN];
__device__ float g_colsum[40];
__device__ float g_tvec[40];
__device__ float g_rep[40];

// ---------------------------------------------------------------------------
__global__ void zero_kernel(int n) {
    int i = blockIdx.x * blockDim.x + threadIdx.x;
    if (i < n) { g_inc[i] = 0; g_outc[i] = 0; }
    if (i < 40) { g_colsum[i] = 0.f; g_rep[i] = 0.f; }
}

__global__ void count_kernel(const int* __restrict__ src,
                             const int* __restrict__ dst, int e) {
    int i = blockIdx.x * blockDim.x + threadIdx.x;
    if (i < e) {
        atomicAdd(&g_outc[src[i]], 1);
        atomicAdd(&g_inc[dst[i]], 1);
    }
}

// single-block exclusive scan of g_inc -> g_rowptr
__global__ void scan_kernel(int n) {
    __shared__ int wsum[32];
    int t = threadIdx.x;
    int lane = t & 31, w = t >> 5;
    int running = 0;
    for (int base = 0; base < n; base += 1024) {
        int v = (base + t < n) ? g_inc[base + t] : 0;
        int x = v;
        #pragma unroll
        for (int off = 1; off < 32; off <<= 1) {
            int y = __shfl_up_sync(0xFFFFFFFFu, x, off);
            if (lane >= off) x += y;
        }
        if (lane == 31) wsum[w] = x;
        __syncthreads();
        if (w == 0) {
            int s = wsum[lane];
            #pragma unroll
            for (int off = 1; off < 32; off <<= 1) {
                int y = __shfl_up_sync(0xFFFFFFFFu, s, off);
                if (lane >= off) s += y;
            }
            wsum[lane] = s;
        }
        __syncthreads();
        int incl = x + (w > 0 ? wsum[w - 1] : 0);
        if (base + t < n) g_rowptr[base + t] = running + (incl - v);
        int total = wsum[31];
        __syncthreads();
        running += total;
    }
    if (t == 0) g_rowptr[n] = running;
}

__global__ void norm_kernel(int n) {
    int i = blockIdx.x * blockDim.x + threadIdx.x;
    if (i < n) {
        g_cursor[i] = g_rowptr[i];
        g_norm_s[i] = rsqrtf((float)max(g_outc[i], 1));
        g_norm_d[i] = rsqrtf((float)max(g_inc[i], 1));
    }
}

__global__ void csr_kernel(const int* __restrict__ src,
                           const int* __restrict__ dst, int e) {
    int i = blockIdx.x * blockDim.x + threadIdx.x;
    if (i < e) {
        int d = dst[i];
        int p = atomicAdd(&g_cursor[d], 1);
        g_esrc[p] = src[i];
    }
}

// ---------------------------------------------------------------------------
// Tiled fp32 GEMM: Y[n][NC] = (A[n][:KD] @ W[KD][NC]) * rowscale[n]
template <int NC, int KD>
__global__ void __launch_bounds__(256)
gemm_kernel(const float* __restrict__ A, const float* __restrict__ W,
            float* __restrict__ Y, const float* __restrict__ rowscale, int n) {
    constexpr int CPT = 5;
    constexpr int TX = NC / CPT;      // 16 (NC=80) or 8 (NC=40)
    constexpr int TY = 256 / TX;      // 16 or 32
    constexpr int RPT = 64 / TY;      // 4 or 2
    constexpr int KC = 16;
    __shared__ float xs[KC][64];
    __shared__ float ws[KC][NC];

    int tid = threadIdx.x;
    int tx = tid % TX, ty = tid / TX;
    int blockRow = blockIdx.x * 64;

    float acc[RPT][CPT];
    #pragma unroll
    for (int i = 0; i < RPT; i++)
        #pragma unroll
        for (int j = 0; j < CPT; j++) acc[i][j] = 0.f;

    for (int kc = 0; kc < KD; kc += KC) {
        {
            int row = tid >> 2;
            int q = tid & 3;
            int gr = blockRow + row;
            float4 v = make_float4(0.f, 0.f, 0.f, 0.f);
            if (gr < n)
                v = *(const float4*)(A + (size_t)gr * KD + kc + q * 4);
            xs[q * 4 + 0][row] = v.x;
            xs[q * 4 + 1][row] = v.y;
            xs[q * 4 + 2][row] = v.z;
            xs[q * 4 + 3][row] = v.w;
        }
        for (int e = tid; e < KC * NC; e += 256) {
            int k = e / NC, j = e % NC;
            ws[k][j] = W[(size_t)(kc + k) * NC + j];
        }
        __syncthreads();
        #pragma unroll
        for (int k = 0; k < KC; k++) {
            float a[RPT], b[CPT];
            #pragma unroll
            for (int i = 0; i < RPT; i++) a[i] = xs[k][ty * RPT + i];
            #pragma unroll
            for (int j = 0; j < CPT; j++) b[j] = ws[k][tx * CPT + j];
            #pragma unroll
            for (int i = 0; i < RPT; i++)
                #pragma unroll
                for (int j = 0; j < CPT; j++) acc[i][j] = fmaf(a[i], b[j], acc[i][j]);
        }
        __syncthreads();
    }
    #pragma unroll
    for (int i = 0; i < RPT; i++) {
        int gr = blockRow + ty * RPT + i;
        if (gr < n) {
            float sc = rowscale[gr];
            #pragma unroll
            for (int j = 0; j < CPT; j++)
                Y[(size_t)gr * NC + tx * CPT + j] = acc[i][j] * sc;
        }
    }
}

// ---------------------------------------------------------------------------
// CSR gather-aggregate: one thread per (node, float4 chunk)
template <int F4>
__global__ void spmm_kernel(const float4* __restrict__ in4,
                            float4* __restrict__ out4,
                            const float* __restrict__ bias, int n) {
    int t = blockIdx.x * blockDim.x + threadIdx.x;
    if (t >= n * F4) return;
    int node = t / F4;
    int f = t - node * F4;
    int rb = g_rowptr[node], re = g_rowptr[node + 1];
    float4 acc = make_float4(0.f, 0.f, 0.f, 0.f);
    int e = rb;
    for (; e + 1 < re; e += 2) {
        int s0 = g_esrc[e], s1 = g_esrc[e + 1];
        float4 v0 = in4[(size_t)s0 * F4 + f];
        float4 v1 = in4[(size_t)s1 * F4 + f];
        acc.x += v0.x + v1.x;
        acc.y += v0.y + v1.y;
        acc.z += v0.z + v1.z;
        acc.w += v0.w + v1.w;
    }
    if (e < re) {
        float4 v = in4[(size_t)g_esrc[e] * F4 + f];
        acc.x += v.x; acc.y += v.y; acc.z += v.z; acc.w += v.w;
    }
    float nd = g_norm_d[node];
    float4 b = *(const float4*)(bias + f * 4);
    float4 o;
    o.x = fmaxf(fmaf(acc.x, nd, b.x), 0.f);
    o.y = fmaxf(fmaf(acc.y, nd, b.y), 0.f);
    o.z = fmaxf(fmaf(acc.z, nd, b.z), 0.f);
    o.w = fmaxf(fmaf(acc.w, nd, b.w), 0.f);
    out4[t] = o;
}

// ---------------------------------------------------------------------------
__global__ void colsum_kernel(const float* __restrict__ h2, int n) {
    int t = blockIdx.x * blockDim.x + threadIdx.x;
    int lane = threadIdx.x & 31;
    float c[40];
    if (t < n) {
        #pragma unroll
        for (int k = 0; k < 10; k++) {
            float4 v = *(const float4*)(h2 + (size_t)t * 40 + k * 4);
            c[k * 4 + 0] = v.x; c[k * 4 + 1] = v.y;
            c[k * 4 + 2] = v.z; c[k * 4 + 3] = v.w;
        }
    } else {
        #pragma unroll
        for (int k = 0; k < 40; k++) c[k] = 0.f;
    }
    #pragma unroll
    for (int k = 0; k < 40; k++) {
        #pragma unroll
        for (int off = 16; off > 0; off >>= 1)
            c[k] += __shfl_xor_sync(0xFFFFFFFFu, c[k], off);
    }
    if (lane == 0)
        #pragma unroll
        for (int k = 0; k < 40; k++) atomicAdd(&g_colsum[k], c[k]);
}

__global__ void tanh_kernel(const float* __restrict__ Wa, int n) {
    __shared__ float m[40];
    int t = threadIdx.x;
    if (t < 40) m[t] = g_colsum[t] * (1.f / (float)n);
    __syncthreads();
    if (t < 40) {
        float g = 0.f;
        #pragma unroll
        for (int i = 0; i < 40; i++) g = fmaf(m[i], Wa[i * 40 + t], g);
        g_tvec[t] = tanhf(g);
    }
}

__global__ void rep_kernel(const float* __restrict__ h2, int n) {
    __shared__ float ts[40];
    if (threadIdx.x < 40) ts[threadIdx.x] = g_tvec[threadIdx.x];
    __syncthreads();
    int t = blockIdx.x * blockDim.x + threadIdx.x;
    int lane = threadIdx.x & 31;
    float c[40];
    if (t < n) {
        #pragma unroll
        for (int k = 0; k < 10; k++) {
            float4 v = *(const float4*)(h2 + (size_t)t * 40 + k * 4);
            c[k * 4 + 0] = v.x; c[k * 4 + 1] = v.y;
            c[k * 4 + 2] = v.z; c[k * 4 + 3] = v.w;
        }
        float dot = 0.f;
        #pragma unroll
        for (int k = 0; k < 40; k++) dot = fmaf(c[k], ts[k], dot);
        float s = 1.f / (1.f + expf(-dot));
        #pragma unroll
        for (int k = 0; k < 40; k++) c[k] *= s;
    } else {
        #pragma unroll
        for (int k = 0; k < 40; k++) c[k] = 0.f;
    }
    #pragma unroll
    for (int k = 0; k < 40; k++) {
        #pragma unroll
        for (int off = 16; off > 0; off >>= 1)
            c[k] += __shfl_xor_sync(0xFFFFFFFFu, c[k], off);
    }
    if (lane == 0)
        #pragma unroll
        for (int k = 0; k < 40; k++) atomicAdd(&g_rep[k], c[k]);
}

__global__ void mlp_kernel(const float* __restrict__ Wm1, const float* __restrict__ bm1,
                           const float* __restrict__ Wm2, const float* __restrict__ bm2,
                           const float* __restrict__ Wm3, const float* __restrict__ bm3,
                           float* __restrict__ out) {
    __shared__ float g1[30];
    __shared__ float g2[10];
    int lane = threadIdx.x;
    if (lane < 30) {
        float v = bm1[lane];
        #pragma unroll
        for (int i = 0; i < 40; i++) v = fmaf(g_rep[i], Wm1[i * 30 + lane], v);
        g1[lane] = fmaxf(v, 0.f);
    }
    __syncthreads();
    if (lane < 10) {
        float v = bm2[lane];
        #pragma unroll
        for (int i = 0; i < 30; i++) v = fmaf(g1[i], Wm2[i * 10 + lane], v);
        g2[lane] = fmaxf(v, 0.f);
    }
    __syncthreads();
    if (lane == 0) {
        float v = bm3[0];
        #pragma unroll
        for (int i = 0; i < 10; i++) v = fmaf(g2[i], Wm3[i], v);
        out[0] = v;
    }
}

// ---------------------------------------------------------------------------
extern "C" void kernel_launch(void* const* d_in, const int* in_sizes, int n_in,
                              void* d_out, int out_size) {
    const float* in_feat = (const float*)d_in[0];
    const int*   src     = (const int*)d_in[1];
    const int*   dst     = (const int*)d_in[2];
    const float* W1      = (const float*)d_in[3];
    const float* b1      = (const float*)d_in[4];
    const float* W2      = (const float*)d_in[5];
    const float* b2      = (const float*)d_in[6];
    const float* Wa      = (const float*)d_in[7];
    const float* Wm1     = (const float*)d_in[8];
    const float* bm1     = (const float*)d_in[9];
    const float* Wm2     = (const float*)d_in[10];
    const float* bm2     = (const float*)d_in[11];
    const float* Wm3     = (const float*)d_in[12];
    const float* bm3     = (const float*)d_in[13];
    float* out = (float*)d_out;

    int n = in_sizes[0] / 256;   // N_NODES
    int e = in_sizes[1];         // N_EDGES

    float* bufA; cudaGetSymbolAddress((void**)&bufA, g_bufA);
    float* bufB; cudaGetSymbolAddress((void**)&bufB, g_bufB);
    float* ns;   cudaGetSymbolAddress((void**)&ns, g_norm_s);

    int nb = (n + 255) / 256;
    int eb = (e + 255) / 256;

    // graph preprocessing (per launch; shared by both conv layers)
    zero_kernel<<<nb, 256>>>(n);
    count_kernel<<<eb, 256>>>(src, dst, e);
    scan_kernel<<<1, 1024>>>(n);
    norm_kernel<<<nb, 256>>>(n);
    csr_kernel<<<eb, 256>>>(src, dst, e);

    // layer 1: h0 = (x @ W1) * norm_s ; h1 = relu(gather * norm_d + b1)
    gemm_kernel<80, 256><<<(n + 63) / 64, 256>>>(in_feat, W1, bufA, ns, n);
    spmm_kernel<20><<<(n * 20 + 255) / 256, 256>>>((const float4*)bufA,
                                                   (float4*)bufB, b1, n);
    // layer 2
    gemm_kernel<40, 80><<<(n + 63) / 64, 256>>>(bufB, W2, bufA, ns, n);
    spmm_kernel<10><<<(n * 10 + 255) / 256, 256>>>((const float4*)bufA,
                                                   (float4*)bufB, b2, n);

    // attention pooling + MLP
    colsum_kernel<<<nb, 256>>>(bufB, n);
    tanh_kernel<<<1, 64>>>(Wa, n);
    rep_kernel<<<nb, 256>>>(bufB, n);
    mlp_kernel<<<1, 32>>>(Wm1, bm1, Wm2, bm2, Wm3, bm3, out);
}

// round 4
// speedup vs baseline: 1.2482x; 1.2482x over previous
#include <cuda_runtime.h>
#include <cuda_fp16.h>
#include <math.h>
#include <type_traits>

// ---------------------------------------------------------------------------
// GCN pipeline. Round-3 state:
//  * no prefix scan: CSR bucket ranges via one global atomic counter
//  * GEMMs tiled 128xNC, 320 thr, all-float4 smem traffic
//  * BOTH aggregation layers gather fp16 rows (fp32 accumulate):
//      layer1 rows 160B, layer2 rows 80B -> 768MB total L2 gather traffic
// ---------------------------------------------------------------------------

#define MAXN 100000
#define MAXE 3200000

__device__ __align__(16) float  g_bufA[MAXN * 80];   // h1 [N,80] fp32 (gemm2 input)
__device__ __align__(16) float  g_bufB[MAXN * 40];   // h2 [N,40] fp32 (attention input)
__device__ __align__(16) __half g_bufH[MAXN * 80];   // fp16 gemm outputs (layer1: 80/row, layer2: 40/row)
__device__ int   g_inc[MAXN];
__device__ int   g_outc[MAXN];
__device__ int   g_rowstart[MAXN];
__device__ int   g_cursor[MAXN];
__device__ int   g_total;
__device__ int   g_esrc[MAXE];
__device__ float g_norm_s[MAXN];
__device__ float g_norm_d[MAXN];
__device__ float g_colsum[40];
__device__ float g_tvec[40];
__device__ float g_rep[40];

// ---------------------------------------------------------------------------
__global__ void zero_kernel(int n) {
    int i = blockIdx.x * blockDim.x + threadIdx.x;
    if (i < n) { g_inc[i] = 0; g_outc[i] = 0; }
    if (i < 40) { g_colsum[i] = 0.f; g_rep[i] = 0.f; }
    if (i == 0) g_total = 0;
}

__global__ void count_kernel(const int* __restrict__ src,
                             const int* __restrict__ dst, int e) {
    int i = blockIdx.x * blockDim.x + threadIdx.x;
    if (i < e) {
        atomicAdd(&g_outc[__ldg(src + i)], 1);
        atomicAdd(&g_inc[__ldg(dst + i)], 1);
    }
}

// per-node contiguous CSR range via one global atomic (bucket order irrelevant)
__global__ void norm_kernel(int n) {
    int i = blockIdx.x * blockDim.x + threadIdx.x;
    if (i < n) {
        int cnt = g_inc[i];
        int start = atomicAdd(&g_total, cnt);
        g_rowstart[i] = start;
        g_cursor[i]   = start;
        g_norm_s[i] = rsqrtf((float)max(g_outc[i], 1));
        g_norm_d[i] = rsqrtf((float)max(cnt, 1));
    }
}

__global__ void csr_kernel(const int* __restrict__ src,
                           const int* __restrict__ dst, int e) {
    int i = blockIdx.x * blockDim.x + threadIdx.x;
    if (i < e) {
        int d = __ldg(dst + i);
        int p = atomicAdd(&g_cursor[d], 1);
        g_esrc[p] = __ldg(src + i);
    }
}

// ---------------------------------------------------------------------------
// Tiled fp32 GEMM: Y[n][NC] = (A[n][:KD] @ W[KD][NC]) * rowscale[n]
// tile 128 x NC, 320 threads, per-thread RPT x 4, all float4 smem traffic.
template <int NC, int KD, typename OutT>
__global__ void __launch_bounds__(320)
gemm_kernel(const float* __restrict__ A, const float* __restrict__ W,
            OutT* __restrict__ Y, const float* __restrict__ rowscale, int n) {
    constexpr int TX = NC / 4;          // 20 (NC=80) or 10 (NC=40)
    constexpr int TY = 320 / TX;        // 16 or 32
    constexpr int RPT = 128 / TY;       // 8 or 4
    constexpr int KC = 16;
    constexpr int XS_STRIDE = 132;      // pad: 16B-aligned rows, de-conflicted stores
    __shared__ float xs[KC][XS_STRIDE];
    __shared__ float ws[KC][NC];

    int tid = threadIdx.x;
    int tx = tid % TX, ty = tid / TX;
    int blockRow = blockIdx.x * 128;

    float acc[RPT][4];
    #pragma unroll
    for (int i = 0; i < RPT; i++)
        #pragma unroll
        for (int j = 0; j < 4; j++) acc[i][j] = 0.f;

    for (int kc = 0; kc < KD; kc += KC) {
        // A tile: 128 rows x 4 quads, transposed into xs[k][row]
        for (int i = tid; i < 512; i += 320) {
            int r = i >> 2, q = i & 3;
            int gr = blockRow + r;
            float4 v = make_float4(0.f, 0.f, 0.f, 0.f);
            if (gr < n) v = *(const float4*)(A + (size_t)gr * KD + kc + q * 4);
            xs[q * 4 + 0][r] = v.x;
            xs[q * 4 + 1][r] = v.y;
            xs[q * 4 + 2][r] = v.z;
            xs[q * 4 + 3][r] = v.w;
        }
        // W chunk: KC x NC
        for (int i = tid; i < KC * NC / 4; i += 320) {
            int k = i / (NC / 4), j = i % (NC / 4);
            *(float4*)&ws[k][j * 4] = *(const float4*)(W + (size_t)(kc + k) * NC + j * 4);
        }
        __syncthreads();
        #pragma unroll
        for (int k = 0; k < KC; k++) {
            float a[RPT];
            #pragma unroll
            for (int i = 0; i < RPT; i += 4) {
                float4 av = *(const float4*)&xs[k][ty * RPT + i];
                a[i + 0] = av.x; a[i + 1] = av.y; a[i + 2] = av.z; a[i + 3] = av.w;
            }
            float4 b = *(const float4*)&ws[k][tx * 4];
            #pragma unroll
            for (int i = 0; i < RPT; i++) {
                acc[i][0] = fmaf(a[i], b.x, acc[i][0]);
                acc[i][1] = fmaf(a[i], b.y, acc[i][1]);
                acc[i][2] = fmaf(a[i], b.z, acc[i][2]);
                acc[i][3] = fmaf(a[i], b.w, acc[i][3]);
            }
        }
        __syncthreads();
    }
    #pragma unroll
    for (int i = 0; i < RPT; i++) {
        int gr = blockRow + ty * RPT + i;
        if (gr < n) {
            float sc = rowscale[gr];
            if constexpr (std::is_same<OutT, __half>::value) {
                __half2 h0 = __floats2half2_rn(acc[i][0] * sc, acc[i][1] * sc);
                __half2 h1 = __floats2half2_rn(acc[i][2] * sc, acc[i][3] * sc);
                uint2 u;
                u.x = *(unsigned*)&h0;
                u.y = *(unsigned*)&h1;
                *(uint2*)(Y + (size_t)gr * NC + tx * 4) = u;
            } else {
                float4 o = make_float4(acc[i][0] * sc, acc[i][1] * sc,
                                       acc[i][2] * sc, acc[i][3] * sc);
                *(float4*)(Y + (size_t)gr * NC + tx * 4) = o;
            }
        }
    }
}

// ---------------------------------------------------------------------------
// CSR gather-aggregate over fp16 rows of width ROW halves (ROW % 8 == 0),
// fp32 accumulate. Thread t -> (node, f) with f indexing a 16B (8-half) chunk.
//   out[node][f*8..f*8+7] = relu(sum_e in[esrc][...]*norm_d + bias)
template <int ROW>
__global__ void __launch_bounds__(256)
spmm_h_kernel(const __half* __restrict__ in, float* __restrict__ out,
              const float* __restrict__ bias, int n) {
    constexpr int F = ROW / 8;
    int t = blockIdx.x * blockDim.x + threadIdx.x;
    if (t >= n * F) return;
    int node = t / F;
    int f = t - node * F;
    int rb = g_rowstart[node];
    int re = rb + g_inc[node];

    float accA[8], accB[8];
    #pragma unroll
    for (int k = 0; k < 8; k++) { accA[k] = 0.f; accB[k] = 0.f; }

    int e = rb;
    for (; e + 1 < re; e += 2) {
        int s0 = g_esrc[e], s1 = g_esrc[e + 1];
        uint4 u0 = *(const uint4*)(in + (size_t)s0 * ROW + f * 8);
        uint4 u1 = *(const uint4*)(in + (size_t)s1 * ROW + f * 8);
        const __half2* h0 = (const __half2*)&u0;
        const __half2* h1 = (const __half2*)&u1;
        #pragma unroll
        for (int k = 0; k < 4; k++) {
            float2 v0 = __half22float2(h0[k]);
            float2 v1 = __half22float2(h1[k]);
            accA[k * 2 + 0] += v0.x; accA[k * 2 + 1] += v0.y;
            accB[k * 2 + 0] += v1.x; accB[k * 2 + 1] += v1.y;
        }
    }
    if (e < re) {
        uint4 u0 = *(const uint4*)(in + (size_t)g_esrc[e] * ROW + f * 8);
        const __half2* h0 = (const __half2*)&u0;
        #pragma unroll
        for (int k = 0; k < 4; k++) {
            float2 v0 = __half22float2(h0[k]);
            accA[k * 2 + 0] += v0.x; accA[k * 2 + 1] += v0.y;
        }
    }
    #pragma unroll
    for (int k = 0; k < 8; k++) accA[k] += accB[k];

    float nd = g_norm_d[node];
    float4 c0 = *(const float4*)(bias + f * 8);
    float4 c1 = *(const float4*)(bias + f * 8 + 4);
    float4 o0, o1;
    o0.x = fmaxf(fmaf(accA[0], nd, c0.x), 0.f);
    o0.y = fmaxf(fmaf(accA[1], nd, c0.y), 0.f);
    o0.z = fmaxf(fmaf(accA[2], nd, c0.z), 0.f);
    o0.w = fmaxf(fmaf(accA[3], nd, c0.w), 0.f);
    o1.x = fmaxf(fmaf(accA[4], nd, c1.x), 0.f);
    o1.y = fmaxf(fmaf(accA[5], nd, c1.y), 0.f);
    o1.z = fmaxf(fmaf(accA[6], nd, c1.z), 0.f);
    o1.w = fmaxf(fmaf(accA[7], nd, c1.w), 0.f);
    *(float4*)(out + (size_t)node * ROW + f * 8)     = o0;
    *(float4*)(out + (size_t)node * ROW + f * 8 + 4) = o1;
}

// ---------------------------------------------------------------------------
__global__ void colsum_kernel(const float* __restrict__ h2, int n) {
    int t = blockIdx.x * blockDim.x + threadIdx.x;
    int lane = threadIdx.x & 31;
    float c[40];
    if (t < n) {
        #pragma unroll
        for (int k = 0; k < 10; k++) {
            float4 v = *(const float4*)(h2 + (size_t)t * 40 + k * 4);
            c[k * 4 + 0] = v.x; c[k * 4 + 1] = v.y;
            c[k * 4 + 2] = v.z; c[k * 4 + 3] = v.w;
        }
    } else {
        #pragma unroll
        for (int k = 0; k < 40; k++) c[k] = 0.f;
    }
    #pragma unroll
    for (int k = 0; k < 40; k++) {
        #pragma unroll
        for (int off = 16; off > 0; off >>= 1)
            c[k] += __shfl_xor_sync(0xFFFFFFFFu, c[k], off);
    }
    if (lane == 0)
        #pragma unroll
        for (int k = 0; k < 40; k++) atomicAdd(&g_colsum[k], c[k]);
}

__global__ void tanh_kernel(const float* __restrict__ Wa, int n) {
    __shared__ float m[40];
    int t = threadIdx.x;
    if (t < 40) m[t] = g_colsum[t] * (1.f / (float)n);
    __syncthreads();
    if (t < 40) {
        float g = 0.f;
        #pragma unroll
        for (int i = 0; i < 40; i++) g = fmaf(m[i], Wa[i * 40 + t], g);
        g_tvec[t] = tanhf(g);
    }
}

__global__ void rep_kernel(const float* __restrict__ h2, int n) {
    __shared__ float ts[40];
    if (threadIdx.x < 40) ts[threadIdx.x] = g_tvec[threadIdx.x];
    __syncthreads();
    int t = blockIdx.x * blockDim.x + threadIdx.x;
    int lane = threadIdx.x & 31;
    float c[40];
    if (t < n) {
        #pragma unroll
        for (int k = 0; k < 10; k++) {
            float4 v = *(const float4*)(h2 + (size_t)t * 40 + k * 4);
            c[k * 4 + 0] = v.x; c[k * 4 + 1] = v.y;
            c[k * 4 + 2] = v.z; c[k * 4 + 3] = v.w;
        }
        float dot = 0.f;
        #pragma unroll
        for (int k = 0; k < 40; k++) dot = fmaf(c[k], ts[k], dot);
        float s = 1.f / (1.f + expf(-dot));
        #pragma unroll
        for (int k = 0; k < 40; k++) c[k] *= s;
    } else {
        #pragma unroll
        for (int k = 0; k < 40; k++) c[k] = 0.f;
    }
    #pragma unroll
    for (int k = 0; k < 40; k++) {
        #pragma unroll
        for (int off = 16; off > 0; off >>= 1)
            c[k] += __shfl_xor_sync(0xFFFFFFFFu, c[k], off);
    }
    if (lane == 0)
        #pragma unroll
        for (int k = 0; k < 40; k++) atomicAdd(&g_rep[k], c[k]);
}

__global__ void mlp_kernel(const float* __restrict__ Wm1, const float* __restrict__ bm1,
                           const float* __restrict__ Wm2, const float* __restrict__ bm2,
                           const float* __restrict__ Wm3, const float* __restrict__ bm3,
                           float* __restrict__ out) {
    __shared__ float g1[30];
    __shared__ float g2[10];
    int lane = threadIdx.x;
    if (lane < 30) {
        float v = bm1[lane];
        #pragma unroll
        for (int i = 0; i < 40; i++) v = fmaf(g_rep[i], Wm1[i * 30 + lane], v);
        g1[lane] = fmaxf(v, 0.f);
    }
    __syncthreads();
    if (lane < 10) {
        float v = bm2[lane];
        #pragma unroll
        for (int i = 0; i < 30; i++) v = fmaf(g1[i], Wm2[i * 10 + lane], v);
        g2[lane] = fmaxf(v, 0.f);
    }
    __syncthreads();
    if (lane == 0) {
        float v = bm3[0];
        #pragma unroll
        for (int i = 0; i < 10; i++) v = fmaf(g2[i], Wm3[i], v);
        out[0] = v;
    }
}

// ---------------------------------------------------------------------------
extern "C" void kernel_launch(void* const* d_in, const int* in_sizes, int n_in,
                              void* d_out, int out_size) {
    const float* in_feat = (const float*)d_in[0];
    const int*   src     = (const int*)d_in[1];
    const int*   dst     = (const int*)d_in[2];
    const float* W1      = (const float*)d_in[3];
    const float* b1      = (const float*)d_in[4];
    const float* W2      = (const float*)d_in[5];
    const float* b2      = (const float*)d_in[6];
    const float* Wa      = (const float*)d_in[7];
    const float* Wm1     = (const float*)d_in[8];
    const float* bm1     = (const float*)d_in[9];
    const float* Wm2     = (const float*)d_in[10];
    const float* bm2     = (const float*)d_in[11];
    const float* Wm3     = (const float*)d_in[12];
    const float* bm3     = (const float*)d_in[13];
    float* out = (float*)d_out;

    int n = in_sizes[0] / 256;   // N_NODES
    int e = in_sizes[1];         // N_EDGES

    float*  bufA; cudaGetSymbolAddress((void**)&bufA, g_bufA);
    float*  bufB; cudaGetSymbolAddress((void**)&bufB, g_bufB);
    __half* bufH; cudaGetSymbolAddress((void**)&bufH, g_bufH);
    float*  ns;   cudaGetSymbolAddress((void**)&ns, g_norm_s);

    int nb = (n + 255) / 256;
    int eb = (e + 255) / 256;

    // graph preprocessing (no scan: atomic bucket ranges)
    zero_kernel<<<nb, 256>>>(n);
    count_kernel<<<eb, 256>>>(src, dst, e);
    norm_kernel<<<nb, 256>>>(n);
    csr_kernel<<<eb, 256>>>(src, dst, e);

    // layer 1: h0 = fp16((x @ W1) * norm_s); h1 = relu(gather*norm_d + b1) fp32
    gemm_kernel<80, 256, __half><<<(n + 127) / 128, 320>>>(in_feat, W1, bufH, ns, n);
    spmm_h_kernel<80><<<(n * 10 + 255) / 256, 256>>>(bufH, bufA, b1, n);
    // layer 2: h1b = fp16((h1 @ W2) * norm_s); h2 = relu(gather*norm_d + b2) fp32
    gemm_kernel<40, 80, __half><<<(n + 127) / 128, 320>>>(bufA, W2, bufH, ns, n);
    spmm_h_kernel<40><<<(n * 5 + 255) / 256, 256>>>(bufH, bufB, b2, n);

    // attention pooling + MLP (h2 = bufB)
    colsum_kernel<<<nb, 256>>>(bufB, n);
    tanh_kernel<<<1, 64>>>(Wa, n);
    rep_kernel<<<nb, 256>>>(bufB, n);
    mlp_kernel<<<1, 32>>>(Wm1, bm1, Wm2, bm2, Wm3, bm3, out);
}

// round 6
// speedup vs baseline: 1.4518x; 1.1631x over previous
#include <cuda_runtime.h>
#include <cuda_fp16.h>
#include <math.h>
#include <type_traits>

// ---------------------------------------------------------------------------
// GCN pipeline. Round-6 changes vs round-4 baseline (567.7us):
//  * both GEMMs on tensor cores via SPLIT-fp16 MMA (3-term Markidis):
//      A split hi/lo in registers from fp32; W pre-split into packed hi/lo.
//      Ah@Wh + Al@Wh + Ah@Wl into fp32 accumulators  ->  ~fp32 accuracy.
//  * GEMM outputs remain fp16 (proven harmless in R4: rel_err 1e-5)
//  * everything else identical to the R4 passing kernel
// ---------------------------------------------------------------------------

#define MAXN 100000
#define MAXE 3200000

__device__ __align__(16) float   g_bufA[MAXN * 80];   // h1 fp32 (gemm2 input)
__device__ __align__(16) float   g_bufB[MAXN * 40];   // h2 fp32 (attention input)
__device__ __align__(16) __half  g_bufH[MAXN * 80];   // gemm out fp16 (l1:80, l2:40)
__device__ __align__(16) __half2 g_wp1h[128 * 80];    // W1 packed hi [KD/2][NC]
__device__ __align__(16) __half2 g_wp1l[128 * 80];    // W1 packed lo
__device__ __align__(16) __half2 g_wp2h[40 * 40];     // W2 packed hi
__device__ __align__(16) __half2 g_wp2l[40 * 40];     // W2 packed lo
__device__ int   g_inc[MAXN];
__device__ int   g_outc[MAXN];
__device__ int   g_rowstart[MAXN];
__device__ int   g_cursor[MAXN];
__device__ int   g_total;
__device__ int   g_esrc[MAXE];
__device__ float g_norm_s[MAXN];
__device__ float g_norm_d[MAXN];
__device__ float g_colsum[40];
__device__ float g_tvec[40];
__device__ float g_rep[40];

// ---------------------------------------------------------------------------
__global__ void zero_kernel(int n) {
    int i = blockIdx.x * blockDim.x + threadIdx.x;
    if (i < n) { g_inc[i] = 0; g_outc[i] = 0; }
    if (i < 40) { g_colsum[i] = 0.f; g_rep[i] = 0.f; }
    if (i == 0) g_total = 0;
}

__global__ void count_kernel(const int* __restrict__ src,
                             const int* __restrict__ dst, int e) {
    int i = blockIdx.x * blockDim.x + threadIdx.x;
    if (i < e) {
        atomicAdd(&g_outc[__ldg(src + i)], 1);
        atomicAdd(&g_inc[__ldg(dst + i)], 1);
    }
}

__global__ void norm_kernel(int n) {
    int i = blockIdx.x * blockDim.x + threadIdx.x;
    if (i < n) {
        int cnt = g_inc[i];
        int start = atomicAdd(&g_total, cnt);
        g_rowstart[i] = start;
        g_cursor[i]   = start;
        g_norm_s[i] = rsqrtf((float)max(g_outc[i], 1));
        g_norm_d[i] = rsqrtf((float)max(cnt, 1));
    }
}

__global__ void csr_kernel(const int* __restrict__ src,
                           const int* __restrict__ dst, int e) {
    int i = blockIdx.x * blockDim.x + threadIdx.x;
    if (i < e) {
        int d = __ldg(dst + i);
        int p = atomicAdd(&g_cursor[d], 1);
        g_esrc[p] = __ldg(src + i);
    }
}

// ---------------------------------------------------------------------------
// pack W [KD][NC] fp32 -> hi/lo half2 k-pairs: {W[2j][c], W[2j+1][c]}
__global__ void wpack_kernel(const float* __restrict__ W,
                             __half2* __restrict__ Whi, __half2* __restrict__ Wlo,
                             int KD2, int NC) {
    int t = blockIdx.x * blockDim.x + threadIdx.x;
    if (t >= KD2 * NC) return;
    int j = t / NC, c = t - j * NC;
    float w0 = W[(size_t)(2 * j) * NC + c];
    float w1 = W[(size_t)(2 * j + 1) * NC + c];
    __half2 h = __floats2half2_rn(w0, w1);
    float2 hf = __half22float2(h);
    Whi[t] = h;
    Wlo[t] = __floats2half2_rn(w0 - hf.x, w1 - hf.y);
}

// split a float pair into hi/lo half2 (packed as unsigned for MMA operands)
__device__ __forceinline__ void split2(float x, float y, unsigned& hi, unsigned& lo) {
    __half2 h = __floats2half2_rn(x, y);
    float2 hf = __half22float2(h);
    __half2 l = __floats2half2_rn(x - hf.x, y - hf.y);
    hi = *(unsigned*)&h;
    lo = *(unsigned*)&l;
}

#define MMA16816(acc, A0, A1, A2, A3, B0, B1)                                   \
    asm volatile(                                                               \
        "mma.sync.aligned.m16n8k16.row.col.f32.f16.f16.f32 "                    \
        "{%0,%1,%2,%3}, {%4,%5,%6,%7}, {%8,%9}, {%0,%1,%2,%3};"                 \
        : "+f"(acc[0]), "+f"(acc[1]), "+f"(acc[2]), "+f"(acc[3])                \
        : "r"(A0), "r"(A1), "r"(A2), "r"(A3), "r"(B0), "r"(B1))

// ---------------------------------------------------------------------------
// Split-fp16 tensor-core GEMM (~fp32 accurate):
//   Y = fp16( (A[n,KD] @ W[KD,NC]) * rowscale[n] ),  A fp32, W pre-split hi/lo.
// Block: 256 thr = 8 warps x 16 rows. W (hi+lo) staged in dynamic smem,
// padded row stride for conflict-free B-fragment loads.
template <int NC, int KD>
__global__ void __launch_bounds__(256)
hgemm_kernel(const float* __restrict__ A,
             const __half2* __restrict__ Wph, const __half2* __restrict__ Wpl,
             __half* __restrict__ Y, const float* __restrict__ rowscale, int n) {
    constexpr int NT = NC / 8;                  // n-tiles (10 or 5)
    constexpr int KT = KD / 16;                 // k-chunks (16 or 5)
    constexpr int WS = (NC == 80) ? 88 : 40;    // padded stride (bank-conflict free)
    extern __shared__ __align__(16) __half2 smem[];
    __half2* wh = smem;                         // [KD/2][WS]
    __half2* wl = smem + (KD / 2) * WS;

    int tid = threadIdx.x;
    int warp = tid >> 5, lane = tid & 31;
    int tig = lane & 3, nn = lane >> 2;

    for (int i = tid; i < (KD / 2) * NC; i += 256) {
        int j = i / NC, c = i - j * NC;
        wh[j * WS + c] = Wph[i];
        wl[j * WS + c] = Wpl[i];
    }
    __syncthreads();

    int row0 = blockIdx.x * 128 + warp * 16;
    int r0 = row0 + nn;                 // rows handled by this thread
    int r1 = r0 + 8;
    bool v0 = r0 < n, v1 = r1 < n;

    float acc[NT][4];
    #pragma unroll
    for (int t = 0; t < NT; t++)
        #pragma unroll
        for (int j = 0; j < 4; j++) acc[t][j] = 0.f;

    const float* a0p = A + (size_t)r0 * KD + 2 * tig;
    const float* a1p = A + (size_t)r1 * KD + 2 * tig;

    for (int kt = 0; kt < KT; kt++) {
        int kb = kt * 16;
        float2 p0 = make_float2(0.f, 0.f), p1 = p0, p2 = p0, p3 = p0;
        if (v0) { p0 = *(const float2*)(a0p + kb);
                  p2 = *(const float2*)(a0p + kb + 8); }
        if (v1) { p1 = *(const float2*)(a1p + kb);
                  p3 = *(const float2*)(a1p + kb + 8); }
        unsigned a0h, a0l, a1h, a1l, a2h, a2l, a3h, a3l;
        split2(p0.x, p0.y, a0h, a0l);
        split2(p1.x, p1.y, a1h, a1l);
        split2(p2.x, p2.y, a2h, a2l);
        split2(p3.x, p3.y, a3h, a3l);

        int kp = kt * 8 + tig;
        #pragma unroll
        for (int t = 0; t < NT; t++) {
            unsigned bh0 = *(const unsigned*)&wh[kp * WS + t * 8 + nn];
            unsigned bh1 = *(const unsigned*)&wh[(kp + 4) * WS + t * 8 + nn];
            unsigned bl0 = *(const unsigned*)&wl[kp * WS + t * 8 + nn];
            unsigned bl1 = *(const unsigned*)&wl[(kp + 4) * WS + t * 8 + nn];
            MMA16816(acc[t], a0h, a1h, a2h, a3h, bh0, bh1);   // Ah @ Wh
            MMA16816(acc[t], a0l, a1l, a2l, a3l, bh0, bh1);   // Al @ Wh
            MMA16816(acc[t], a0h, a1h, a2h, a3h, bl0, bl1);   // Ah @ Wl
        }
    }

    float s0 = v0 ? rowscale[r0] : 0.f;
    float s1 = v1 ? rowscale[r1] : 0.f;
    int cb = 2 * tig;
    #pragma unroll
    for (int t = 0; t < NT; t++) {
        if (v0) {
            __half2 h = __floats2half2_rn(acc[t][0] * s0, acc[t][1] * s0);
            *(unsigned*)(Y + (size_t)r0 * NC + t * 8 + cb) = *(unsigned*)&h;
        }
        if (v1) {
            __half2 h = __floats2half2_rn(acc[t][2] * s1, acc[t][3] * s1);
            *(unsigned*)(Y + (size_t)r1 * NC + t * 8 + cb) = *(unsigned*)&h;
        }
    }
}

// ---------------------------------------------------------------------------
// CSR gather-aggregate over fp16 rows (ROW halves), fp32 accumulate + output.
// Thread t -> (node, f); f indexes a 16B (8-half) chunk.
template <int ROW>
__global__ void __launch_bounds__(256)
spmm_h_kernel(const __half* __restrict__ in, float* __restrict__ out,
              const float* __restrict__ bias, int n) {
    constexpr int F = ROW / 8;
    int t = blockIdx.x * blockDim.x + threadIdx.x;
    if (t >= n * F) return;
    int node = t / F;
    int f = t - node * F;
    int rb = g_rowstart[node];
    int re = rb + g_inc[node];

    float accA[8], accB[8];
    #pragma unroll
    for (int k = 0; k < 8; k++) { accA[k] = 0.f; accB[k] = 0.f; }

    int e = rb;
    for (; e + 1 < re; e += 2) {
        int s0 = g_esrc[e], s1 = g_esrc[e + 1];
        uint4 u0 = *(const uint4*)(in + (size_t)s0 * ROW + f * 8);
        uint4 u1 = *(const uint4*)(in + (size_t)s1 * ROW + f * 8);
        const __half2* h0 = (const __half2*)&u0;
        const __half2* h1 = (const __half2*)&u1;
        #pragma unroll
        for (int k = 0; k < 4; k++) {
            float2 w0 = __half22float2(h0[k]);
            float2 w1 = __half22float2(h1[k]);
            accA[k * 2 + 0] += w0.x; accA[k * 2 + 1] += w0.y;
            accB[k * 2 + 0] += w1.x; accB[k * 2 + 1] += w1.y;
        }
    }
    if (e < re) {
        uint4 u0 = *(const uint4*)(in + (size_t)g_esrc[e] * ROW + f * 8);
        const __half2* h0 = (const __half2*)&u0;
        #pragma unroll
        for (int k = 0; k < 4; k++) {
            float2 w0 = __half22float2(h0[k]);
            accA[k * 2 + 0] += w0.x; accA[k * 2 + 1] += w0.y;
        }
    }
    #pragma unroll
    for (int k = 0; k < 8; k++) accA[k] += accB[k];

    float nd = g_norm_d[node];
    float4 c0 = *(const float4*)(bias + f * 8);
    float4 c1 = *(const float4*)(bias + f * 8 + 4);
    float4 o0, o1;
    o0.x = fmaxf(fmaf(accA[0], nd, c0.x), 0.f);
    o0.y = fmaxf(fmaf(accA[1], nd, c0.y), 0.f);
    o0.z = fmaxf(fmaf(accA[2], nd, c0.z), 0.f);
    o0.w = fmaxf(fmaf(accA[3], nd, c0.w), 0.f);
    o1.x = fmaxf(fmaf(accA[4], nd, c1.x), 0.f);
    o1.y = fmaxf(fmaf(accA[5], nd, c1.y), 0.f);
    o1.z = fmaxf(fmaf(accA[6], nd, c1.z), 0.f);
    o1.w = fmaxf(fmaf(accA[7], nd, c1.w), 0.f);
    *(float4*)(out + (size_t)node * ROW + f * 8)     = o0;
    *(float4*)(out + (size_t)node * ROW + f * 8 + 4) = o1;
}

// ---------------------------------------------------------------------------
__global__ void colsum_kernel(const float* __restrict__ h2, int n) {
    int t = blockIdx.x * blockDim.x + threadIdx.x;
    int lane = threadIdx.x & 31;
    float c[40];
    if (t < n) {
        #pragma unroll
        for (int k = 0; k < 10; k++) {
            float4 v = *(const float4*)(h2 + (size_t)t * 40 + k * 4);
            c[k * 4 + 0] = v.x; c[k * 4 + 1] = v.y;
            c[k * 4 + 2] = v.z; c[k * 4 + 3] = v.w;
        }
    } else {
        #pragma unroll
        for (int k = 0; k < 40; k++) c[k] = 0.f;
    }
    #pragma unroll
    for (int k = 0; k < 40; k++) {
        #pragma unroll
        for (int off = 16; off > 0; off >>= 1)
            c[k] += __shfl_xor_sync(0xFFFFFFFFu, c[k], off);
    }
    if (lane == 0)
        #pragma unroll
        for (int k = 0; k < 40; k++) atomicAdd(&g_colsum[k], c[k]);
}

__global__ void tanh_kernel(const float* __restrict__ Wa, int n) {
    __shared__ float m[40];
    int t = threadIdx.x;
    if (t < 40) m[t] = g_colsum[t] * (1.f / (float)n);
    __syncthreads();
    if (t < 40) {
        float g = 0.f;
        #pragma unroll
        for (int i = 0; i < 40; i++) g = fmaf(m[i], Wa[i * 40 + t], g);
        g_tvec[t] = tanhf(g);
    }
}

__global__ void rep_kernel(const float* __restrict__ h2, int n) {
    __shared__ float ts[40];
    if (threadIdx.x < 40) ts[threadIdx.x] = g_tvec[threadIdx.x];
    __syncthreads();
    int t = blockIdx.x * blockDim.x + threadIdx.x;
    int lane = threadIdx.x & 31;
    float c[40];
    if (t < n) {
        #pragma unroll
        for (int k = 0; k < 10; k++) {
            float4 v = *(const float4*)(h2 + (size_t)t * 40 + k * 4);
            c[k * 4 + 0] = v.x; c[k * 4 + 1] = v.y;
            c[k * 4 + 2] = v.z; c[k * 4 + 3] = v.w;
        }
        float dot = 0.f;
        #pragma unroll
        for (int k = 0; k < 40; k++) dot = fmaf(c[k], ts[k], dot);
        float s = 1.f / (1.f + expf(-dot));
        #pragma unroll
        for (int k = 0; k < 40; k++) c[k] *= s;
    } else {
        #pragma unroll
        for (int k = 0; k < 40; k++) c[k] = 0.f;
    }
    #pragma unroll
    for (int k = 0; k < 40; k++) {
        #pragma unroll
        for (int off = 16; off > 0; off >>= 1)
            c[k] += __shfl_xor_sync(0xFFFFFFFFu, c[k], off);
    }
    if (lane == 0)
        #pragma unroll
        for (int k = 0; k < 40; k++) atomicAdd(&g_rep[k], c[k]);
}

__global__ void mlp_kernel(const float* __restrict__ Wm1, const float* __restrict__ bm1,
                           const float* __restrict__ Wm2, const float* __restrict__ bm2,
                           const float* __restrict__ Wm3, const float* __restrict__ bm3,
                           float* __restrict__ out) {
    __shared__ float g1[30];
    __shared__ float g2[10];
    int lane = threadIdx.x;
    if (lane < 30) {
        float v = bm1[lane];
        #pragma unroll
        for (int i = 0; i < 40; i++) v = fmaf(g_rep[i], Wm1[i * 30 + lane], v);
        g1[lane] = fmaxf(v, 0.f);
    }
    __syncthreads();
    if (lane < 10) {
        float v = bm2[lane];
        #pragma unroll
        for (int i = 0; i < 30; i++) v = fmaf(g1[i], Wm2[i * 10 + lane], v);
        g2[lane] = fmaxf(v, 0.f);
    }
    __syncthreads();
    if (lane == 0) {
        float v = bm3[0];
        #pragma unroll
        for (int i = 0; i < 10; i++) v = fmaf(g2[i], Wm3[i], v);
        out[0] = v;
    }
}

// ---------------------------------------------------------------------------
extern "C" void kernel_launch(void* const* d_in, const int* in_sizes, int n_in,
                              void* d_out, int out_size) {
    const float* in_feat = (const float*)d_in[0];
    const int*   src     = (const int*)d_in[1];
    const int*   dst     = (const int*)d_in[2];
    const float* W1      = (const float*)d_in[3];
    const float* b1      = (const float*)d_in[4];
    const float* W2      = (const float*)d_in[5];
    const float* b2      = (const float*)d_in[6];
    const float* Wa      = (const float*)d_in[7];
    const float* Wm1     = (const float*)d_in[8];
    const float* bm1     = (const float*)d_in[9];
    const float* Wm2     = (const float*)d_in[10];
    const float* bm2     = (const float*)d_in[11];
    const float* Wm3     = (const float*)d_in[12];
    const float* bm3     = (const float*)d_in[13];
    float* out = (float*)d_out;

    int n = in_sizes[0] / 256;   // N_NODES
    int e = in_sizes[1];         // N_EDGES

    float*   bufA; cudaGetSymbolAddress((void**)&bufA, g_bufA);
    float*   bufB; cudaGetSymbolAddress((void**)&bufB, g_bufB);
    __half*  bufH; cudaGetSymbolAddress((void**)&bufH, g_bufH);
    __half2* wp1h; cudaGetSymbolAddress((void**)&wp1h, g_wp1h);
    __half2* wp1l; cudaGetSymbolAddress((void**)&wp1l, g_wp1l);
    __half2* wp2h; cudaGetSymbolAddress((void**)&wp2h, g_wp2h);
    __half2* wp2l; cudaGetSymbolAddress((void**)&wp2l, g_wp2l);
    float*   ns;   cudaGetSymbolAddress((void**)&ns, g_norm_s);

    // dynamic smem sizes: 2 arrays x (KD/2) x padded-stride x 4B
    const int smem1 = 2 * 128 * 88 * 4;    // 90112 B (needs opt-in)
    const int smem2 = 2 * 40 * 40 * 4;     // 12800 B
    cudaFuncSetAttribute(hgemm_kernel<80, 256>,
                         cudaFuncAttributeMaxDynamicSharedMemorySize, smem1);

    int nb = (n + 255) / 256;
    int eb = (e + 255) / 256;

    // graph preprocessing
    zero_kernel<<<nb, 256>>>(n);
    count_kernel<<<eb, 256>>>(src, dst, e);
    norm_kernel<<<nb, 256>>>(n);
    csr_kernel<<<eb, 256>>>(src, dst, e);

    // weight packing (hi/lo split)
    wpack_kernel<<<(128 * 80 + 255) / 256, 256>>>(W1, wp1h, wp1l, 128, 80);
    wpack_kernel<<<(40 * 40 + 255) / 256, 256>>>(W2, wp2h, wp2l, 40, 40);

    // layer 1: bufH = fp16((x @ W1) * norm_s); h1 = fp32 relu(gather*norm_d + b1)
    hgemm_kernel<80, 256><<<(n + 127) / 128, 256, smem1>>>(in_feat, wp1h, wp1l,
                                                           bufH, ns, n);
    spmm_h_kernel<80><<<(n * 10 + 255) / 256, 256>>>(bufH, bufA, b1, n);
    // layer 2: bufH = fp16((h1 @ W2) * norm_s); h2 = fp32 relu(gather*norm_d + b2)
    hgemm_kernel<40, 80><<<(n + 127) / 128, 256, smem2>>>(bufA, wp2h, wp2l,
                                                          bufH, ns, n);
    spmm_h_kernel<40><<<(n * 5 + 255) / 256, 256>>>(bufH, bufB, b2, n);

    // attention pooling + MLP (h2 = bufB)
    colsum_kernel<<<nb, 256>>>(bufB, n);
    tanh_kernel<<<1, 64>>>(Wa, n);
    rep_kernel<<<nb, 256>>>(bufB, n);
    mlp_kernel<<<1, 32>>>(Wm1, bm1, Wm2, bm2, Wm3, bm3, out);
}

// round 7
// speedup vs baseline: 1.4672x; 1.0106x over previous
#include <cuda_runtime.h>
#include <cuda_fp16.h>
#include <math.h>
#include <type_traits>

// ---------------------------------------------------------------------------
// GCN pipeline. Round-7 changes vs round-6 (488.1us):
//  * multi-stream fork inside graph capture: {wpack -> hgemm1} overlaps
//    csr_kernel (both depend only on norm_kernel); event fork/join pattern.
//  * SpMM gather loop 4-deep unrolled (4 outstanding L2 loads per thread)
//  * numerics identical to R6 (split-fp16 MMA, fp32 elsewhere)
// ---------------------------------------------------------------------------

#define MAXN 100000
#define MAXE 3200000

__device__ __align__(16) float   g_bufA[MAXN * 80];   // h1 fp32 (gemm2 input)
__device__ __align__(16) float   g_bufB[MAXN * 40];   // h2 fp32 (attention input)
__device__ __align__(16) __half  g_bufH[MAXN * 80];   // gemm out fp16 (l1:80, l2:40)
__device__ __align__(16) __half2 g_wp1h[128 * 80];    // W1 packed hi [KD/2][NC]
__device__ __align__(16) __half2 g_wp1l[128 * 80];    // W1 packed lo
__device__ __align__(16) __half2 g_wp2h[40 * 40];     // W2 packed hi
__device__ __align__(16) __half2 g_wp2l[40 * 40];     // W2 packed lo
__device__ int   g_inc[MAXN];
__device__ int   g_outc[MAXN];
__device__ int   g_rowstart[MAXN];
__device__ int   g_cursor[MAXN];
__device__ int   g_total;
__device__ int   g_esrc[MAXE];
__device__ float g_norm_s[MAXN];
__device__ float g_norm_d[MAXN];
__device__ float g_colsum[40];
__device__ float g_tvec[40];
__device__ float g_rep[40];

// ---------------------------------------------------------------------------
__global__ void zero_kernel(int n) {
    int i = blockIdx.x * blockDim.x + threadIdx.x;
    if (i < n) { g_inc[i] = 0; g_outc[i] = 0; }
    if (i < 40) { g_colsum[i] = 0.f; g_rep[i] = 0.f; }
    if (i == 0) g_total = 0;
}

__global__ void count_kernel(const int* __restrict__ src,
                             const int* __restrict__ dst, int e) {
    int i = blockIdx.x * blockDim.x + threadIdx.x;
    if (i < e) {
        atomicAdd(&g_outc[__ldg(src + i)], 1);
        atomicAdd(&g_inc[__ldg(dst + i)], 1);
    }
}

__global__ void norm_kernel(int n) {
    int i = blockIdx.x * blockDim.x + threadIdx.x;
    if (i < n) {
        int cnt = g_inc[i];
        int start = atomicAdd(&g_total, cnt);
        g_rowstart[i] = start;
        g_cursor[i]   = start;
        g_norm_s[i] = rsqrtf((float)max(g_outc[i], 1));
        g_norm_d[i] = rsqrtf((float)max(cnt, 1));
    }
}

__global__ void csr_kernel(const int* __restrict__ src,
                           const int* __restrict__ dst, int e) {
    int i = blockIdx.x * blockDim.x + threadIdx.x;
    if (i < e) {
        int d = __ldg(dst + i);
        int p = atomicAdd(&g_cursor[d], 1);
        g_esrc[p] = __ldg(src + i);
    }
}

// ---------------------------------------------------------------------------
// pack W [KD][NC] fp32 -> hi/lo half2 k-pairs: {W[2j][c], W[2j+1][c]}
__global__ void wpack_kernel(const float* __restrict__ W,
                             __half2* __restrict__ Whi, __half2* __restrict__ Wlo,
                             int KD2, int NC) {
    int t = blockIdx.x * blockDim.x + threadIdx.x;
    if (t >= KD2 * NC) return;
    int j = t / NC, c = t - j * NC;
    float w0 = W[(size_t)(2 * j) * NC + c];
    float w1 = W[(size_t)(2 * j + 1) * NC + c];
    __half2 h = __floats2half2_rn(w0, w1);
    float2 hf = __half22float2(h);
    Whi[t] = h;
    Wlo[t] = __floats2half2_rn(w0 - hf.x, w1 - hf.y);
}

// split a float pair into hi/lo half2 (packed as unsigned for MMA operands)
__device__ __forceinline__ void split2(float x, float y, unsigned& hi, unsigned& lo) {
    __half2 h = __floats2half2_rn(x, y);
    float2 hf = __half22float2(h);
    __half2 l = __floats2half2_rn(x - hf.x, y - hf.y);
    hi = *(unsigned*)&h;
    lo = *(unsigned*)&l;
}

#define MMA16816(acc, A0, A1, A2, A3, B0, B1)                                   \
    asm volatile(                                                               \
        "mma.sync.aligned.m16n8k16.row.col.f32.f16.f16.f32 "                    \
        "{%0,%1,%2,%3}, {%4,%5,%6,%7}, {%8,%9}, {%0,%1,%2,%3};"                 \
        : "+f"(acc[0]), "+f"(acc[1]), "+f"(acc[2]), "+f"(acc[3])                \
        : "r"(A0), "r"(A1), "r"(A2), "r"(A3), "r"(B0), "r"(B1))

// ---------------------------------------------------------------------------
// Split-fp16 tensor-core GEMM (~fp32 accurate):
//   Y = fp16( (A[n,KD] @ W[KD,NC]) * rowscale[n] ),  A fp32, W pre-split hi/lo.
template <int NC, int KD>
__global__ void __launch_bounds__(256)
hgemm_kernel(const float* __restrict__ A,
             const __half2* __restrict__ Wph, const __half2* __restrict__ Wpl,
             __half* __restrict__ Y, const float* __restrict__ rowscale, int n) {
    constexpr int NT = NC / 8;                  // n-tiles (10 or 5)
    constexpr int KT = KD / 16;                 // k-chunks (16 or 5)
    constexpr int WS = (NC == 80) ? 88 : 40;    // padded stride (bank-conflict free)
    extern __shared__ __align__(16) __half2 smem[];
    __half2* wh = smem;                         // [KD/2][WS]
    __half2* wl = smem + (KD / 2) * WS;

    int tid = threadIdx.x;
    int warp = tid >> 5, lane = tid & 31;
    int tig = lane & 3, nn = lane >> 2;

    for (int i = tid; i < (KD / 2) * NC; i += 256) {
        int j = i / NC, c = i - j * NC;
        wh[j * WS + c] = Wph[i];
        wl[j * WS + c] = Wpl[i];
    }
    __syncthreads();

    int row0 = blockIdx.x * 128 + warp * 16;
    int r0 = row0 + nn;                 // rows handled by this thread
    int r1 = r0 + 8;
    bool v0 = r0 < n, v1 = r1 < n;

    float acc[NT][4];
    #pragma unroll
    for (int t = 0; t < NT; t++)
        #pragma unroll
        for (int j = 0; j < 4; j++) acc[t][j] = 0.f;

    const float* a0p = A + (size_t)r0 * KD + 2 * tig;
    const float* a1p = A + (size_t)r1 * KD + 2 * tig;

    for (int kt = 0; kt < KT; kt++) {
        int kb = kt * 16;
        float2 p0 = make_float2(0.f, 0.f), p1 = p0, p2 = p0, p3 = p0;
        if (v0) { p0 = *(const float2*)(a0p + kb);
                  p2 = *(const float2*)(a0p + kb + 8); }
        if (v1) { p1 = *(const float2*)(a1p + kb);
                  p3 = *(const float2*)(a1p + kb + 8); }
        unsigned a0h, a0l, a1h, a1l, a2h, a2l, a3h, a3l;
        split2(p0.x, p0.y, a0h, a0l);
        split2(p1.x, p1.y, a1h, a1l);
        split2(p2.x, p2.y, a2h, a2l);
        split2(p3.x, p3.y, a3h, a3l);

        int kp = kt * 8 + tig;
        #pragma unroll
        for (int t = 0; t < NT; t++) {
            unsigned bh0 = *(const unsigned*)&wh[kp * WS + t * 8 + nn];
            unsigned bh1 = *(const unsigned*)&wh[(kp + 4) * WS + t * 8 + nn];
            unsigned bl0 = *(const unsigned*)&wl[kp * WS + t * 8 + nn];
            unsigned bl1 = *(const unsigned*)&wl[(kp + 4) * WS + t * 8 + nn];
            MMA16816(acc[t], a0h, a1h, a2h, a3h, bh0, bh1);   // Ah @ Wh
            MMA16816(acc[t], a0l, a1l, a2l, a3l, bh0, bh1);   // Al @ Wh
            MMA16816(acc[t], a0h, a1h, a2h, a3h, bl0, bl1);   // Ah @ Wl
        }
    }

    float s0 = v0 ? rowscale[r0] : 0.f;
    float s1 = v1 ? rowscale[r1] : 0.f;
    int cb = 2 * tig;
    #pragma unroll
    for (int t = 0; t < NT; t++) {
        if (v0) {
            __half2 h = __floats2half2_rn(acc[t][0] * s0, acc[t][1] * s0);
            *(unsigned*)(Y + (size_t)r0 * NC + t * 8 + cb) = *(unsigned*)&h;
        }
        if (v1) {
            __half2 h = __floats2half2_rn(acc[t][2] * s1, acc[t][3] * s1);
            *(unsigned*)(Y + (size_t)r1 * NC + t * 8 + cb) = *(unsigned*)&h;
        }
    }
}

// ---------------------------------------------------------------------------
// CSR gather-aggregate over fp16 rows (ROW halves), fp32 accumulate + output.
// Thread t -> (node, f); f indexes a 16B (8-half) chunk. 4-deep unroll.
template <int ROW>
__global__ void __launch_bounds__(256)
spmm_h_kernel(const __half* __restrict__ in, float* __restrict__ out,
              const float* __restrict__ bias, int n) {
    constexpr int F = ROW / 8;
    int t = blockIdx.x * blockDim.x + threadIdx.x;
    if (t >= n * F) return;
    int node = t / F;
    int f = t - node * F;
    int rb = g_rowstart[node];
    int re = rb + g_inc[node];

    float accA[8], accB[8];
    #pragma unroll
    for (int k = 0; k < 8; k++) { accA[k] = 0.f; accB[k] = 0.f; }

    int e = rb;
    for (; e + 3 < re; e += 4) {
        int s0 = g_esrc[e],     s1 = g_esrc[e + 1];
        int s2 = g_esrc[e + 2], s3 = g_esrc[e + 3];
        uint4 u0 = *(const uint4*)(in + (size_t)s0 * ROW + f * 8);
        uint4 u1 = *(const uint4*)(in + (size_t)s1 * ROW + f * 8);
        uint4 u2 = *(const uint4*)(in + (size_t)s2 * ROW + f * 8);
        uint4 u3 = *(const uint4*)(in + (size_t)s3 * ROW + f * 8);
        const __half2* h0 = (const __half2*)&u0;
        const __half2* h1 = (const __half2*)&u1;
        const __half2* h2 = (const __half2*)&u2;
        const __half2* h3 = (const __half2*)&u3;
        #pragma unroll
        for (int k = 0; k < 4; k++) {
            float2 w0 = __half22float2(h0[k]);
            float2 w1 = __half22float2(h1[k]);
            float2 w2 = __half22float2(h2[k]);
            float2 w3 = __half22float2(h3[k]);
            accA[k * 2 + 0] += w0.x + w2.x;
            accA[k * 2 + 1] += w0.y + w2.y;
            accB[k * 2 + 0] += w1.x + w3.x;
            accB[k * 2 + 1] += w1.y + w3.y;
        }
    }
    for (; e < re; e++) {
        uint4 u0 = *(const uint4*)(in + (size_t)g_esrc[e] * ROW + f * 8);
        const __half2* h0 = (const __half2*)&u0;
        #pragma unroll
        for (int k = 0; k < 4; k++) {
            float2 w0 = __half22float2(h0[k]);
            accA[k * 2 + 0] += w0.x; accA[k * 2 + 1] += w0.y;
        }
    }
    #pragma unroll
    for (int k = 0; k < 8; k++) accA[k] += accB[k];

    float nd = g_norm_d[node];
    float4 c0 = *(const float4*)(bias + f * 8);
    float4 c1 = *(const float4*)(bias + f * 8 + 4);
    float4 o0, o1;
    o0.x = fmaxf(fmaf(accA[0], nd, c0.x), 0.f);
    o0.y = fmaxf(fmaf(accA[1], nd, c0.y), 0.f);
    o0.z = fmaxf(fmaf(accA[2], nd, c0.z), 0.f);
    o0.w = fmaxf(fmaf(accA[3], nd, c0.w), 0.f);
    o1.x = fmaxf(fmaf(accA[4], nd, c1.x), 0.f);
    o1.y = fmaxf(fmaf(accA[5], nd, c1.y), 0.f);
    o1.z = fmaxf(fmaf(accA[6], nd, c1.z), 0.f);
    o1.w = fmaxf(fmaf(accA[7], nd, c1.w), 0.f);
    *(float4*)(out + (size_t)node * ROW + f * 8)     = o0;
    *(float4*)(out + (size_t)node * ROW + f * 8 + 4) = o1;
}

// ---------------------------------------------------------------------------
__global__ void colsum_kernel(const float* __restrict__ h2, int n) {
    int t = blockIdx.x * blockDim.x + threadIdx.x;
    int lane = threadIdx.x & 31;
    float c[40];
    if (t < n) {
        #pragma unroll
        for (int k = 0; k < 10; k++) {
            float4 v = *(const float4*)(h2 + (size_t)t * 40 + k * 4);
            c[k * 4 + 0] = v.x; c[k * 4 + 1] = v.y;
            c[k * 4 + 2] = v.z; c[k * 4 + 3] = v.w;
        }
    } else {
        #pragma unroll
        for (int k = 0; k < 40; k++) c[k] = 0.f;
    }
    #pragma unroll
    for (int k = 0; k < 40; k++) {
        #pragma unroll
        for (int off = 16; off > 0; off >>= 1)
            c[k] += __shfl_xor_sync(0xFFFFFFFFu, c[k], off);
    }
    if (lane == 0)
        #pragma unroll
        for (int k = 0; k < 40; k++) atomicAdd(&g_colsum[k], c[k]);
}

__global__ void tanh_kernel(const float* __restrict__ Wa, int n) {
    __shared__ float m[40];
    int t = threadIdx.x;
    if (t < 40) m[t] = g_colsum[t] * (1.f / (float)n);
    __syncthreads();
    if (t < 40) {
        float g = 0.f;
        #pragma unroll
        for (int i = 0; i < 40; i++) g = fmaf(m[i], Wa[i * 40 + t], g);
        g_tvec[t] = tanhf(g);
    }
}

__global__ void rep_kernel(const float* __restrict__ h2, int n) {
    __shared__ float ts[40];
    if (threadIdx.x < 40) ts[threadIdx.x] = g_tvec[threadIdx.x];
    __syncthreads();
    int t = blockIdx.x * blockDim.x + threadIdx.x;
    int lane = threadIdx.x & 31;
    float c[40];
    if (t < n) {
        #pragma unroll
        for (int k = 0; k < 10; k++) {
            float4 v = *(const float4*)(h2 + (size_t)t * 40 + k * 4);
            c[k * 4 + 0] = v.x; c[k * 4 + 1] = v.y;
            c[k * 4 + 2] = v.z; c[k * 4 + 3] = v.w;
        }
        float dot = 0.f;
        #pragma unroll
        for (int k = 0; k < 40; k++) dot = fmaf(c[k], ts[k], dot);
        float s = 1.f / (1.f + expf(-dot));
        #pragma unroll
        for (int k = 0; k < 40; k++) c[k] *= s;
    } else {
        #pragma unroll
        for (int k = 0; k < 40; k++) c[k] = 0.f;
    }
    #pragma unroll
    for (int k = 0; k < 40; k++) {
        #pragma unroll
        for (int off = 16; off > 0; off >>= 1)
            c[k] += __shfl_xor_sync(0xFFFFFFFFu, c[k], off);
    }
    if (lane == 0)
        #pragma unroll
        for (int k = 0; k < 40; k++) atomicAdd(&g_rep[k], c[k]);
}

__global__ void mlp_kernel(const float* __restrict__ Wm1, const float* __restrict__ bm1,
                           const float* __restrict__ Wm2, const float* __restrict__ bm2,
                           const float* __restrict__ Wm3, const float* __restrict__ bm3,
                           float* __restrict__ out) {
    __shared__ float g1[30];
    __shared__ float g2[10];
    int lane = threadIdx.x;
    if (lane < 30) {
        float v = bm1[lane];
        #pragma unroll
        for (int i = 0; i < 40; i++) v = fmaf(g_rep[i], Wm1[i * 30 + lane], v);
        g1[lane] = fmaxf(v, 0.f);
    }
    __syncthreads();
    if (lane < 10) {
        float v = bm2[lane];
        #pragma unroll
        for (int i = 0; i < 30; i++) v = fmaf(g1[i], Wm2[i * 10 + lane], v);
        g2[lane] = fmaxf(v, 0.f);
    }
    __syncthreads();
    if (lane == 0) {
        float v = bm3[0];
        #pragma unroll
        for (int i = 0; i < 10; i++) v = fmaf(g2[i], Wm3[i], v);
        out[0] = v;
    }
}

// ---------------------------------------------------------------------------
extern "C" void kernel_launch(void* const* d_in, const int* in_sizes, int n_in,
                              void* d_out, int out_size) {
    const float* in_feat = (const float*)d_in[0];
    const int*   src     = (const int*)d_in[1];
    const int*   dst     = (const int*)d_in[2];
    const float* W1      = (const float*)d_in[3];
    const float* b1      = (const float*)d_in[4];
    const float* W2      = (const float*)d_in[5];
    const float* b2      = (const float*)d_in[6];
    const float* Wa      = (const float*)d_in[7];
    const float* Wm1     = (const float*)d_in[8];
    const float* bm1     = (const float*)d_in[9];
    const float* Wm2     = (const float*)d_in[10];
    const float* bm2     = (const float*)d_in[11];
    const float* Wm3     = (const float*)d_in[12];
    const float* bm3     = (const float*)d_in[13];
    float* out = (float*)d_out;

    int n = in_sizes[0] / 256;   // N_NODES
    int e = in_sizes[1];         // N_EDGES

    float*   bufA; cudaGetSymbolAddress((void**)&bufA, g_bufA);
    float*   bufB; cudaGetSymbolAddress((void**)&bufB, g_bufB);
    __half*  bufH; cudaGetSymbolAddress((void**)&bufH, g_bufH);
    __half2* wp1h; cudaGetSymbolAddress((void**)&wp1h, g_wp1h);
    __half2* wp1l; cudaGetSymbolAddress((void**)&wp1l, g_wp1l);
    __half2* wp2h; cudaGetSymbolAddress((void**)&wp2h, g_wp2h);
    __half2* wp2l; cudaGetSymbolAddress((void**)&wp2l, g_wp2l);
    float*   ns;   cudaGetSymbolAddress((void**)&ns, g_norm_s);

    const int smem1 = 2 * 128 * 88 * 4;    // 90112 B (opt-in)
    const int smem2 = 2 * 40 * 40 * 4;     // 12800 B
    cudaFuncSetAttribute(hgemm_kernel<80, 256>,
                         cudaFuncAttributeMaxDynamicSharedMemorySize, smem1);

    int nb = (n + 255) / 256;
    int eb = (e + 255) / 256;

    // side stream + fork/join events (created per call; capturable pattern).
    // NonBlocking avoids legacy-default-stream implicit serialization.
    cudaStream_t s1;
    cudaStreamCreateWithFlags(&s1, cudaStreamNonBlocking);
    cudaEvent_t evStart, evNorm, evGemm1;
    cudaEventCreateWithFlags(&evStart, cudaEventDisableTiming);
    cudaEventCreateWithFlags(&evNorm,  cudaEventDisableTiming);
    cudaEventCreateWithFlags(&evGemm1, cudaEventDisableTiming);

    // main stream (legacy default): preprocessing chain
    cudaEventRecord(evStart, 0);
    zero_kernel<<<nb, 256>>>(n);
    count_kernel<<<eb, 256>>>(src, dst, e);
    norm_kernel<<<nb, 256>>>(n);
    cudaEventRecord(evNorm, 0);

    // side stream: wpack (independent) then gemm1 (needs norm_s only)
    cudaStreamWaitEvent(s1, evStart, 0);
    wpack_kernel<<<(128 * 80 + 255) / 256, 256, 0, s1>>>(W1, wp1h, wp1l, 128, 80);
    wpack_kernel<<<(40 * 40 + 255) / 256, 256, 0, s1>>>(W2, wp2h, wp2l, 40, 40);
    cudaStreamWaitEvent(s1, evNorm, 0);
    hgemm_kernel<80, 256><<<(n + 127) / 128, 256, smem1, s1>>>(in_feat, wp1h, wp1l,
                                                               bufH, ns, n);
    cudaEventRecord(evGemm1, s1);

    // main stream: CSR fill overlaps gemm1
    csr_kernel<<<eb, 256>>>(src, dst, e);

    // join: spmm1 needs both csr (main) and gemm1 (side)
    cudaStreamWaitEvent(0, evGemm1, 0);
    spmm_h_kernel<80><<<(n * 10 + 255) / 256, 256>>>(bufH, bufA, b1, n);

    // layer 2 (serial tail)
    hgemm_kernel<40, 80><<<(n + 127) / 128, 256, smem2>>>(bufA, wp2h, wp2l,
                                                          bufH, ns, n);
    spmm_h_kernel<40><<<(n * 5 + 255) / 256, 256>>>(bufH, bufB, b2, n);

    // attention pooling + MLP (h2 = bufB)
    colsum_kernel<<<nb, 256>>>(bufB, n);
    tanh_kernel<<<1, 64>>>(Wa, n);
    rep_kernel<<<nb, 256>>>(bufB, n);
    mlp_kernel<<<1, 32>>>(Wm1, bm1, Wm2, bm2, Wm3, bm3, out);
}